// round 4
// baseline (speedup 1.0000x reference)
#include <cuda_runtime.h>

#define N_NODES 100000
#define N_EDGES 800000
#define DIM     64
#define HEADS   4
#define DH      16

typedef unsigned long long u64;
typedef unsigned int       u32;

// L2-resident scratch (GB300 L2 ~126MB; Q+K+V = 76.8MB)
__device__ float g_Q[N_NODES * DIM];
__device__ float g_K[N_NODES * DIM];
__device__ float g_V[N_NODES * DIM];
__device__ float g_norm[N_NODES * HEADS];

// ---------------------------------------------------------------------------
// Packed fp32x2 FMA (Blackwell FFMA2).
// ---------------------------------------------------------------------------
__device__ __forceinline__ u64 ffma2(u64 a, u64 b, u64 c) {
    u64 d;
    asm("fma.rn.f32x2 %0, %1, %2, %3;" : "=l"(d) : "l"(a), "l"(b), "l"(c));
    return d;
}
__device__ __forceinline__ u64 pack2(float x) {
    u64 r; u32 xi = __float_as_uint(x);
    asm("mov.b64 %0, {%1, %1};" : "=l"(r) : "r"(xi));
    return r;
}

// ---------------------------------------------------------------------------
// Register-blocked QKV GEMM, one W matrix per block (blockIdx.y selects it).
// 256 threads, 256-node tile. Thread (tx,ty) computes 8 nodes x 8 cols.
// Per k: 8 scalar LDS (A) + 2 LDS.128 (B) + 32 FFMA2 on independent accs.
// Grid = 391 x 3 -> 1173 short blocks -> ~4 full waves, ~1% tail.
// ---------------------------------------------------------------------------
__global__ __launch_bounds__(256, 2) void gemm_qkv(
    const float* __restrict__ E,
    const float* __restrict__ Wq, const float* __restrict__ Wk,
    const float* __restrict__ Wv)
{
    extern __shared__ float sh[];
    float* sE = sh;                // [256][65]
    float* sW = sh + 256 * 65;     // [64][64]

    int t    = threadIdx.x;
    int m    = blockIdx.y;
    int base = blockIdx.x * 256;

    const float4* Wsrc = (m == 0) ? (const float4*)Wq
                       : (m == 1) ? (const float4*)Wk : (const float4*)Wv;
    #pragma unroll
    for (int i = 0; i < 4; i++)
        ((float4*)sW)[t + i * 256] = Wsrc[t + i * 256];

    // Load E tile (float4 global reads, scalar smem stores due to pad-65 rows)
    for (int i = t; i < 4096; i += 256) {
        int r  = i >> 4;
        int c4 = i & 15;
        int node = base + r;
        float4 v = (node < N_NODES) ? ((const float4*)E)[node * 16 + c4]
                                    : make_float4(0.f, 0.f, 0.f, 0.f);
        float* d = &sE[r * 65 + c4 * 4];
        d[0] = v.x; d[1] = v.y; d[2] = v.z; d[3] = v.w;
    }
    __syncthreads();

    int tx = t & 7, ty = t >> 3;
    int c0 = tx * 8;
    int n0 = ty * 8;

    u64 acc[8][4];
    #pragma unroll
    for (int i = 0; i < 8; i++)
        #pragma unroll
        for (int j = 0; j < 4; j++) acc[i][j] = 0ull;

    #pragma unroll 4
    for (int k = 0; k < 64; k++) {
        ulonglong2 b0 = *(const ulonglong2*)&sW[k * 64 + c0];
        ulonglong2 b1 = *(const ulonglong2*)&sW[k * 64 + c0 + 4];
        #pragma unroll
        for (int i = 0; i < 8; i++) {
            u64 a2 = pack2(sE[(n0 + i) * 65 + k]);
            acc[i][0] = ffma2(a2, b0.x, acc[i][0]);
            acc[i][1] = ffma2(a2, b0.y, acc[i][1]);
            acc[i][2] = ffma2(a2, b1.x, acc[i][2]);
            acc[i][3] = ffma2(a2, b1.y, acc[i][3]);
        }
    }

    float* O = (m == 0) ? g_Q : (m == 1) ? g_K : g_V;
    #pragma unroll
    for (int i = 0; i < 8; i++) {
        int node = base + n0 + i;
        if (node < N_NODES) {
            float4* o = (float4*)(O + node * 64 + c0);
            u64 a0 = acc[i][0], a1 = acc[i][1];
            u64 a2 = acc[i][2], a3 = acc[i][3];
            o[0] = make_float4(__uint_as_float((u32)a0),
                               __uint_as_float((u32)(a0 >> 32)),
                               __uint_as_float((u32)a1),
                               __uint_as_float((u32)(a1 >> 32)));
            o[1] = make_float4(__uint_as_float((u32)a2),
                               __uint_as_float((u32)(a2 >> 32)),
                               __uint_as_float((u32)a3),
                               __uint_as_float((u32)(a3 >> 32)));
        }
    }
}

// ---------------------------------------------------------------------------
// Vector reduction (no return): 1 L2 transaction for 4 floats.
// ---------------------------------------------------------------------------
__device__ __forceinline__ void red_add_v4(float* addr, float a, float b,
                                           float c, float d) {
    asm volatile("red.global.add.v4.f32 [%0], {%1, %2, %3, %4};"
                 :: "l"(addr), "f"(a), "f"(b), "f"(c), "f"(d)
                 : "memory");
}

// ---------------------------------------------------------------------------
// Pass 1: thread per EDGE. All 4 heads: expAtt = exp(clip(q.k)); one float4
// att store; one red.v4 into norm[r*4..r*4+3].
// ---------------------------------------------------------------------------
__global__ void edge_logits(const int* __restrict__ rows, const int* __restrict__ cols,
                            float* __restrict__ att) {
    int e = blockIdx.x * blockDim.x + threadIdx.x;
    if (e >= N_EDGES) return;
    int r = rows[e], c = cols[e];

    const float4* q = (const float4*)(g_Q + r * DIM);
    const float4* k = (const float4*)(g_K + c * DIM);

    float ex[4];
    #pragma unroll
    for (int h = 0; h < 4; h++) {
        float s = 0.0f;
        #pragma unroll
        for (int i = 0; i < 4; i++) {
            float4 a = q[h * 4 + i], b = k[h * 4 + i];
            s += a.x * b.x + a.y * b.y + a.z * b.z + a.w * b.w;
        }
        s = fminf(fmaxf(s, -10.0f), 10.0f);
        ex[h] = __expf(s);
    }

    ((float4*)att)[e] = make_float4(ex[0], ex[1], ex[2], ex[3]);
    red_add_v4(&g_norm[r * HEADS], ex[0], ex[1], ex[2], ex[3]);
}

// ---------------------------------------------------------------------------
// Pass 2: thread per EDGE. att = expAtt/(norm[row]+eps) (float4 RW);
// res[row] += att*V[col] with 16 red.v4 in flight.
// ---------------------------------------------------------------------------
__global__ void edge_accum(const int* __restrict__ rows, const int* __restrict__ cols,
                           float* __restrict__ res, float* __restrict__ att) {
    int e = blockIdx.x * blockDim.x + threadIdx.x;
    if (e >= N_EDGES) return;
    int r = rows[e], c = cols[e];

    float4 ex = ((float4*)att)[e];
    float4 nm = *(const float4*)&g_norm[r * HEADS];
    float a[4];
    a[0] = ex.x / (nm.x + 1e-8f);
    a[1] = ex.y / (nm.y + 1e-8f);
    a[2] = ex.z / (nm.z + 1e-8f);
    a[3] = ex.w / (nm.w + 1e-8f);
    ((float4*)att)[e] = make_float4(a[0], a[1], a[2], a[3]);

    const float4* v = (const float4*)(g_V + c * DIM);
    float* dst = res + r * DIM;
    #pragma unroll
    for (int h = 0; h < 4; h++) {
        float ah = a[h];
        #pragma unroll
        for (int i = 0; i < 4; i++) {
            float4 vv = v[h * 4 + i];
            red_add_v4(dst + h * 16 + i * 4, ah * vv.x, ah * vv.y,
                       ah * vv.z, ah * vv.w);
        }
    }
}

// ---------------------------------------------------------------------------
extern "C" void kernel_launch(void* const* d_in, const int* in_sizes, int n_in,
                              void* d_out, int out_size) {
    const float* embeds = (const float*)d_in[0];
    const float* Wq     = (const float*)d_in[1];
    const float* Wk     = (const float*)d_in[2];
    const float* Wv     = (const float*)d_in[3];
    const int*   rows   = (const int*)d_in[4];
    const int*   cols   = (const int*)d_in[5];

    float* res = (float*)d_out;                    // [N_NODES, 64]
    float* att = (float*)d_out + N_NODES * DIM;    // [N_EDGES, 4]

    // 1) zero res + norm
    void* pNorm;
    cudaGetSymbolAddress(&pNorm, g_norm);
    cudaMemsetAsync(res, 0, (size_t)N_NODES * DIM * sizeof(float));
    cudaMemsetAsync(pNorm, 0, (size_t)N_NODES * HEADS * sizeof(float));

    // 2) register-blocked QKV projection, one matrix per block (y-dim)
    const int smem_bytes = (256 * 65 + 64 * 64) * sizeof(float);   // 82944
    cudaFuncSetAttribute(gemm_qkv, cudaFuncAttributeMaxDynamicSharedMemorySize,
                         smem_bytes);
    dim3 gg((N_NODES + 255) / 256, 3);
    gemm_qkv<<<gg, 256, smem_bytes>>>(embeds, Wq, Wk, Wv);

    // 3) logits + segment norm (thread per edge)
    int blocks = (N_EDGES + 255) / 256;
    edge_logits<<<blocks, 256>>>(rows, cols, att);

    // 4) normalize + scatter-accumulate (thread per edge)
    edge_accum<<<blocks, 256>>>(rows, cols, res, att);
}

// round 5
// speedup vs baseline: 1.2958x; 1.2958x over previous
#include <cuda_runtime.h>

#define N_NODES 100000
#define N_EDGES 800000
#define DIM     64
#define HEADS   4
#define DH      16

typedef unsigned long long u64;
typedef unsigned int       u32;

// L2-resident scratch (GB300 L2 ~126MB; Q+K+V = 76.8MB)
__device__ float g_Q[N_NODES * DIM];
__device__ float g_K[N_NODES * DIM];
__device__ float g_V[N_NODES * DIM];
__device__ float g_norm[N_NODES * HEADS];

// ---------------------------------------------------------------------------
// Packed fp32x2 FMA (Blackwell FFMA2).
// ---------------------------------------------------------------------------
__device__ __forceinline__ u64 ffma2(u64 a, u64 b, u64 c) {
    u64 d;
    asm("fma.rn.f32x2 %0, %1, %2, %3;" : "=l"(d) : "l"(a), "l"(b), "l"(c));
    return d;
}
__device__ __forceinline__ u64 pack2(float x) {
    u64 r; u32 xi = __float_as_uint(x);
    asm("mov.b64 %0, {%1, %1};" : "=l"(r) : "r"(xi));
    return r;
}

// ---------------------------------------------------------------------------
// Register-blocked QKV GEMM, one W matrix per block (blockIdx.y).
// 128-node tile, 256 threads; thread (tx=t&7, ty=t>>3) computes
// 4 nodes x 8 cols. smem ~50KB -> 4 blocks/SM -> 32 warps/SM.
// Per k: 4 scalar LDS (A, x8 broadcast) + 2 LDS.128 (B) + 16 FFMA2.
// ---------------------------------------------------------------------------
__global__ __launch_bounds__(256, 4) void gemm_qkv(
    const float* __restrict__ E,
    const float* __restrict__ Wq, const float* __restrict__ Wk,
    const float* __restrict__ Wv)
{
    extern __shared__ float sh[];
    float* sE = sh;                // [128][65]
    float* sW = sh + 128 * 65;     // [64][64]

    int t    = threadIdx.x;
    int m    = blockIdx.y;
    int base = blockIdx.x * 128;

    const float4* Wsrc = (m == 0) ? (const float4*)Wq
                       : (m == 1) ? (const float4*)Wk : (const float4*)Wv;
    #pragma unroll
    for (int i = 0; i < 4; i++)
        ((float4*)sW)[t + i * 256] = Wsrc[t + i * 256];

    // Load 128-node E tile (float4 global reads, scalar smem stores, pad 65)
    for (int i = t; i < 2048; i += 256) {
        int r  = i >> 4;
        int c4 = i & 15;
        int node = base + r;
        float4 v = (node < N_NODES) ? ((const float4*)E)[node * 16 + c4]
                                    : make_float4(0.f, 0.f, 0.f, 0.f);
        float* d = &sE[r * 65 + c4 * 4];
        d[0] = v.x; d[1] = v.y; d[2] = v.z; d[3] = v.w;
    }
    __syncthreads();

    int tx = t & 7, ty = t >> 3;
    int c0 = tx * 8;                // 8 output cols
    int n0 = ty * 4;                // 4 nodes

    u64 acc[4][4];
    #pragma unroll
    for (int i = 0; i < 4; i++)
        #pragma unroll
        for (int j = 0; j < 4; j++) acc[i][j] = 0ull;

    #pragma unroll 4
    for (int k = 0; k < 64; k++) {
        ulonglong2 b0 = *(const ulonglong2*)&sW[k * 64 + c0];
        ulonglong2 b1 = *(const ulonglong2*)&sW[k * 64 + c0 + 4];
        #pragma unroll
        for (int i = 0; i < 4; i++) {
            u64 a2 = pack2(sE[(n0 + i) * 65 + k]);
            acc[i][0] = ffma2(a2, b0.x, acc[i][0]);
            acc[i][1] = ffma2(a2, b0.y, acc[i][1]);
            acc[i][2] = ffma2(a2, b1.x, acc[i][2]);
            acc[i][3] = ffma2(a2, b1.y, acc[i][3]);
        }
    }

    float* O = (m == 0) ? g_Q : (m == 1) ? g_K : g_V;
    #pragma unroll
    for (int i = 0; i < 4; i++) {
        int node = base + n0 + i;
        if (node < N_NODES) {
            float4* o = (float4*)(O + node * 64 + c0);
            u64 a0 = acc[i][0], a1 = acc[i][1];
            u64 a2 = acc[i][2], a3 = acc[i][3];
            o[0] = make_float4(__uint_as_float((u32)a0),
                               __uint_as_float((u32)(a0 >> 32)),
                               __uint_as_float((u32)a1),
                               __uint_as_float((u32)(a1 >> 32)));
            o[1] = make_float4(__uint_as_float((u32)a2),
                               __uint_as_float((u32)(a2 >> 32)),
                               __uint_as_float((u32)a3),
                               __uint_as_float((u32)(a3 >> 32)));
        }
    }
}

// ---------------------------------------------------------------------------
// Pass 1: thread per (edge, head). expAtt = exp(clip(q.k)); scalar atomic
// into norm. 4 consecutive lanes share a row -> coalesced 64B gathers.
// ---------------------------------------------------------------------------
__global__ void edge_logits(const int* __restrict__ rows, const int* __restrict__ cols,
                            float* __restrict__ att) {
    int idx = blockIdx.x * blockDim.x + threadIdx.x;
    if (idx >= N_EDGES * HEADS) return;
    int e = idx >> 2, h = idx & 3;
    int r = rows[e], c = cols[e];

    const float4* q = (const float4*)(g_Q + r * DIM + h * DH);
    const float4* k = (const float4*)(g_K + c * DIM + h * DH);

    float s = 0.0f;
    #pragma unroll
    for (int i = 0; i < 4; i++) {
        float4 a = q[i], b = k[i];
        s += a.x * b.x + a.y * b.y + a.z * b.z + a.w * b.w;
    }
    s = fminf(fmaxf(s, -10.0f), 10.0f);
    float ex = __expf(s);

    att[idx] = ex;                               // staged; normalized in pass 2
    atomicAdd(&g_norm[r * HEADS + h], ex);
}

// ---------------------------------------------------------------------------
// Vector reduction (no return): 1 L2 transaction for 4 floats.
// ---------------------------------------------------------------------------
__device__ __forceinline__ void red_add_v4(float* addr, float a, float b,
                                           float c, float d) {
    asm volatile("red.global.add.v4.f32 [%0], {%1, %2, %3, %4};"
                 :: "l"(addr), "f"(a), "f"(b), "f"(c), "f"(d)
                 : "memory");
}

// ---------------------------------------------------------------------------
// Pass 2: thread per (edge, head). att = expAtt/(norm+eps);
// res[row] += att * V[col] via 4 red.v4.
// ---------------------------------------------------------------------------
__global__ void edge_accum(const int* __restrict__ rows, const int* __restrict__ cols,
                           float* __restrict__ res, float* __restrict__ att) {
    int idx = blockIdx.x * blockDim.x + threadIdx.x;
    if (idx >= N_EDGES * HEADS) return;
    int e = idx >> 2, h = idx & 3;
    int r = rows[e], c = cols[e];

    float ex = att[idx];
    float a  = ex / (g_norm[r * HEADS + h] + 1e-8f);
    att[idx] = a;

    const float4* v = (const float4*)(g_V + c * DIM + h * DH);
    float* dst = res + r * DIM + h * DH;
    #pragma unroll
    for (int i = 0; i < 4; i++) {
        float4 vv = v[i];
        red_add_v4(dst + i * 4, a * vv.x, a * vv.y, a * vv.z, a * vv.w);
    }
}

// ---------------------------------------------------------------------------
extern "C" void kernel_launch(void* const* d_in, const int* in_sizes, int n_in,
                              void* d_out, int out_size) {
    const float* embeds = (const float*)d_in[0];
    const float* Wq     = (const float*)d_in[1];
    const float* Wk     = (const float*)d_in[2];
    const float* Wv     = (const float*)d_in[3];
    const int*   rows   = (const int*)d_in[4];
    const int*   cols   = (const int*)d_in[5];

    float* res = (float*)d_out;                    // [N_NODES, 64]
    float* att = (float*)d_out + N_NODES * DIM;    // [N_EDGES, 4]

    // 1) zero res + norm
    void* pNorm;
    cudaGetSymbolAddress(&pNorm, g_norm);
    cudaMemsetAsync(res, 0, (size_t)N_NODES * DIM * sizeof(float));
    cudaMemsetAsync(pNorm, 0, (size_t)N_NODES * HEADS * sizeof(float));

    // 2) register-blocked QKV projection, 128-node tiles, 4 blocks/SM
    const int smem_bytes = (128 * 65 + 64 * 64) * sizeof(float);   // 49664
    cudaFuncSetAttribute(gemm_qkv, cudaFuncAttributeMaxDynamicSharedMemorySize,
                         smem_bytes);
    dim3 gg((N_NODES + 127) / 128, 3);
    gemm_qkv<<<gg, 256, smem_bytes>>>(embeds, Wq, Wk, Wv);

    // 3) logits + segment norm (thread per (edge,head))
    int edge_blocks = (N_EDGES * HEADS + 255) / 256;
    edge_logits<<<edge_blocks, 256>>>(rows, cols, att);

    // 4) normalize + scatter-accumulate (thread per (edge,head))
    edge_accum<<<edge_blocks, 256>>>(rows, cols, res, att);
}

// round 6
// speedup vs baseline: 1.3990x; 1.0796x over previous
#include <cuda_runtime.h>

#define N_NODES 100000
#define N_EDGES 800000
#define DIM     64
#define HEADS   4
#define DH      16

typedef unsigned long long u64;
typedef unsigned int       u32;

// L2-resident scratch (GB300 L2 ~126MB; Q+K+V = 76.8MB)
__device__ float g_Q[N_NODES * DIM];
__device__ float g_K[N_NODES * DIM];
__device__ float g_V[N_NODES * DIM];
__device__ float g_norm[N_NODES * HEADS];

// ---------------------------------------------------------------------------
// Packed fp32x2 FMA (Blackwell FFMA2).
// ---------------------------------------------------------------------------
__device__ __forceinline__ u64 ffma2(u64 a, u64 b, u64 c) {
    u64 d;
    asm("fma.rn.f32x2 %0, %1, %2, %3;" : "=l"(d) : "l"(a), "l"(b), "l"(c));
    return d;
}
__device__ __forceinline__ u64 pack2(float x) {
    u64 r; u32 xi = __float_as_uint(x);
    asm("mov.b64 %0, {%1, %1};" : "=l"(r) : "r"(xi));
    return r;
}

// ---------------------------------------------------------------------------
// Register-blocked QKV GEMM, one W matrix per block (blockIdx.y).
// 256-node tile, 256 threads; thread (tx=t&7, ty=t>>3) computes 8 nodes x
// 8 cols. k unrolled by 4: A loaded as float4 (LDS.128) per node and held
// in regs across the 4 k-steps -> 16 LDS.128 per 128 FFMA2 (was 40 LDS).
// sE padded to 68 floats/row: rows offset by 4 banks -> the 4 distinct
// ty-row A addresses per warp are conflict-free.
// ---------------------------------------------------------------------------
__global__ __launch_bounds__(256, 2) void gemm_qkv(
    const float* __restrict__ E,
    const float* __restrict__ Wq, const float* __restrict__ Wk,
    const float* __restrict__ Wv)
{
    extern __shared__ float sh[];
    float* sE = sh;                // [256][68]
    float* sW = sh + 256 * 68;     // [64][64]

    int t    = threadIdx.x;
    int m    = blockIdx.y;
    int base = blockIdx.x * 256;

    const float4* Wsrc = (m == 0) ? (const float4*)Wq
                       : (m == 1) ? (const float4*)Wk : (const float4*)Wv;
    #pragma unroll
    for (int i = 0; i < 4; i++)
        ((float4*)sW)[t + i * 256] = Wsrc[t + i * 256];

    // Load 256-node E tile (float4 in, float4 smem stores; 68-pad keeps
    // 16B alignment since 68 % 4 == 0)
    for (int i = t; i < 4096; i += 256) {
        int r  = i >> 4;
        int c4 = i & 15;
        int node = base + r;
        float4 v = (node < N_NODES) ? ((const float4*)E)[node * 16 + c4]
                                    : make_float4(0.f, 0.f, 0.f, 0.f);
        *(float4*)&sE[r * 68 + c4 * 4] = v;
    }
    __syncthreads();

    int tx = t & 7, ty = t >> 3;
    int c0 = tx * 8;
    int n0 = ty * 8;

    u64 acc[8][4];
    #pragma unroll
    for (int i = 0; i < 8; i++)
        #pragma unroll
        for (int j = 0; j < 4; j++) acc[i][j] = 0ull;

    for (int k = 0; k < 64; k += 4) {
        float4 a4[8];
        #pragma unroll
        for (int i = 0; i < 8; i++)
            a4[i] = *(const float4*)&sE[(n0 + i) * 68 + k];

        #pragma unroll
        for (int kk = 0; kk < 4; kk++) {
            ulonglong2 b0 = *(const ulonglong2*)&sW[(k + kk) * 64 + c0];
            ulonglong2 b1 = *(const ulonglong2*)&sW[(k + kk) * 64 + c0 + 4];
            #pragma unroll
            for (int i = 0; i < 8; i++) {
                float av = (kk == 0) ? a4[i].x : (kk == 1) ? a4[i].y
                         : (kk == 2) ? a4[i].z : a4[i].w;
                u64 a2 = pack2(av);
                acc[i][0] = ffma2(a2, b0.x, acc[i][0]);
                acc[i][1] = ffma2(a2, b0.y, acc[i][1]);
                acc[i][2] = ffma2(a2, b1.x, acc[i][2]);
                acc[i][3] = ffma2(a2, b1.y, acc[i][3]);
            }
        }
    }

    float* O = (m == 0) ? g_Q : (m == 1) ? g_K : g_V;
    #pragma unroll
    for (int i = 0; i < 8; i++) {
        int node = base + n0 + i;
        if (node < N_NODES) {
            float4* o = (float4*)(O + node * 64 + c0);
            u64 a0 = acc[i][0], a1 = acc[i][1];
            u64 a2 = acc[i][2], a3 = acc[i][3];
            o[0] = make_float4(__uint_as_float((u32)a0),
                               __uint_as_float((u32)(a0 >> 32)),
                               __uint_as_float((u32)a1),
                               __uint_as_float((u32)(a1 >> 32)));
            o[1] = make_float4(__uint_as_float((u32)a2),
                               __uint_as_float((u32)(a2 >> 32)),
                               __uint_as_float((u32)a3),
                               __uint_as_float((u32)(a3 >> 32)));
        }
    }
}

// ---------------------------------------------------------------------------
// Pass 1: thread per (edge, head). expAtt = exp(clip(q.k)); scalar atomic
// into norm. 4 consecutive lanes share a row -> coalesced gathers.
// ---------------------------------------------------------------------------
__global__ void edge_logits(const int* __restrict__ rows, const int* __restrict__ cols,
                            float* __restrict__ att) {
    int idx = blockIdx.x * blockDim.x + threadIdx.x;
    if (idx >= N_EDGES * HEADS) return;
    int e = idx >> 2, h = idx & 3;
    int r = rows[e], c = cols[e];

    const float4* q = (const float4*)(g_Q + r * DIM + h * DH);
    const float4* k = (const float4*)(g_K + c * DIM + h * DH);

    float s = 0.0f;
    #pragma unroll
    for (int i = 0; i < 4; i++) {
        float4 a = q[i], b = k[i];
        s += a.x * b.x + a.y * b.y + a.z * b.z + a.w * b.w;
    }
    s = fminf(fmaxf(s, -10.0f), 10.0f);
    float ex = __expf(s);

    att[idx] = ex;                               // staged; normalized in pass 2
    atomicAdd(&g_norm[r * HEADS + h], ex);
}

// ---------------------------------------------------------------------------
// Vector reduction (no return): 1 L2 transaction for 4 floats.
// ---------------------------------------------------------------------------
__device__ __forceinline__ void red_add_v4(float* addr, float a, float b,
                                           float c, float d) {
    asm volatile("red.global.add.v4.f32 [%0], {%1, %2, %3, %4};"
                 :: "l"(addr), "f"(a), "f"(b), "f"(c), "f"(d)
                 : "memory");
}

// ---------------------------------------------------------------------------
// Pass 2: each thread handles TWO (edge,head) units (idx, idx + 1.6M) with
// interleaved loads -> 2x memory-level parallelism (issue was 9%).
// ---------------------------------------------------------------------------
#define ACCUM_HALF (N_EDGES * HEADS / 2)

__global__ void edge_accum(const int* __restrict__ rows, const int* __restrict__ cols,
                           float* __restrict__ res, float* __restrict__ att) {
    int idx = blockIdx.x * blockDim.x + threadIdx.x;
    if (idx >= ACCUM_HALF) return;
    int idx2 = idx + ACCUM_HALF;

    int e0 = idx  >> 2, h0 = idx  & 3;
    int e1 = idx2 >> 2, h1 = idx2 & 3;
    int r0 = rows[e0], c0 = cols[e0];
    int r1 = rows[e1], c1 = cols[e1];

    float ex0 = att[idx];
    float ex1 = att[idx2];
    float nm0 = g_norm[r0 * HEADS + h0];
    float nm1 = g_norm[r1 * HEADS + h1];

    const float4* v0 = (const float4*)(g_V + c0 * DIM + h0 * DH);
    const float4* v1 = (const float4*)(g_V + c1 * DIM + h1 * DH);
    float4 vv0[4], vv1[4];
    #pragma unroll
    for (int i = 0; i < 4; i++) { vv0[i] = v0[i]; vv1[i] = v1[i]; }

    float a0 = ex0 / (nm0 + 1e-8f);
    float a1 = ex1 / (nm1 + 1e-8f);
    att[idx]  = a0;
    att[idx2] = a1;

    float* dst0 = res + r0 * DIM + h0 * DH;
    float* dst1 = res + r1 * DIM + h1 * DH;
    #pragma unroll
    for (int i = 0; i < 4; i++) {
        red_add_v4(dst0 + i * 4, a0 * vv0[i].x, a0 * vv0[i].y,
                   a0 * vv0[i].z, a0 * vv0[i].w);
        red_add_v4(dst1 + i * 4, a1 * vv1[i].x, a1 * vv1[i].y,
                   a1 * vv1[i].z, a1 * vv1[i].w);
    }
}

// ---------------------------------------------------------------------------
extern "C" void kernel_launch(void* const* d_in, const int* in_sizes, int n_in,
                              void* d_out, int out_size) {
    const float* embeds = (const float*)d_in[0];
    const float* Wq     = (const float*)d_in[1];
    const float* Wk     = (const float*)d_in[2];
    const float* Wv     = (const float*)d_in[3];
    const int*   rows   = (const int*)d_in[4];
    const int*   cols   = (const int*)d_in[5];

    float* res = (float*)d_out;                    // [N_NODES, 64]
    float* att = (float*)d_out + N_NODES * DIM;    // [N_EDGES, 4]

    // 1) zero res + norm
    void* pNorm;
    cudaGetSymbolAddress(&pNorm, g_norm);
    cudaMemsetAsync(res, 0, (size_t)N_NODES * DIM * sizeof(float));
    cudaMemsetAsync(pNorm, 0, (size_t)N_NODES * HEADS * sizeof(float));

    // 2) register-blocked QKV projection, 256-node tiles, k-unroll-4
    const int smem_bytes = (256 * 68 + 64 * 64) * sizeof(float);   // 86016
    cudaFuncSetAttribute(gemm_qkv, cudaFuncAttributeMaxDynamicSharedMemorySize,
                         smem_bytes);
    dim3 gg((N_NODES + 255) / 256, 3);
    gemm_qkv<<<gg, 256, smem_bytes>>>(embeds, Wq, Wk, Wv);

    // 3) logits + segment norm (thread per (edge,head))
    int edge_blocks = (N_EDGES * HEADS + 255) / 256;
    edge_logits<<<edge_blocks, 256>>>(rows, cols, att);

    // 4) normalize + scatter-accumulate (2 units per thread)
    int accum_blocks = (ACCUM_HALF + 255) / 256;
    edge_accum<<<accum_blocks, 256>>>(rows, cols, res, att);
}